// round 13
// baseline (speedup 1.0000x reference)
#include <cuda_runtime.h>
#include <cuda_bf16.h>
#include <cstdint>
#include <math.h>

// ---------------------------------------------------------------------------
// LSTM decoder — mma.sync bf16 split hi/lo (3-pass), ldmatrix, cp.async.
// R13: warp-specialized fused kernel. 128 CTAs x 384 threads:
//   warps 0-7  = consumer: the R10 recurrence (barrier id 1, 256 thr)
//   warps 8-11 = producer: Z = A@Wz^T + bias row-tiles (barrier id 2, 128 thr)
// Producers fill the consumer's idle tensor slots; per-t readiness counters.
// ---------------------------------------------------------------------------

#define BATCH 512
#define SEQL  512
#define HID   256
#define MF    17
#define G4    1024
#define KIN   273
#define NBT   8
#define BT    64
#define NROWS (SEQL * BATCH)
#define KPU   132            // u32 per bf16 row (264 bf16); 528B rows, LDSM-clean

typedef unsigned long long ull;

__device__ float          g_Z[(size_t)NROWS * G4];          // 1 GB
__device__ float          g_corr[G4];
__device__ int            g_cnt[NBT];
__device__ int            g_zdone[SEQL];
__device__ __nv_bfloat16  g_Ahi[(size_t)NROWS * HID];
__device__ __nv_bfloat16  g_Alo[(size_t)NROWS * HID];
__device__ __nv_bfloat16  g_hh_hi[(size_t)SEQL * BATCH * HID];
__device__ __nv_bfloat16  g_hh_lo[(size_t)SEQL * BATCH * HID];
__device__ __nv_bfloat16  g_Wzhi[G4 * HID], g_Wzlo[G4 * HID];   // z-proj (plain)
__device__ __nv_bfloat16  g_Wq_hi[G4 * HID], g_Wq_lo[G4 * HID]; // Whh (permuted)
__device__ __nv_bfloat16  g_Wp_hi[G4 * HID], g_Wp_lo[G4 * HID]; // Wc  (permuted)

__device__ __forceinline__ float sigm(float x) {
    return __fdividef(1.0f, 1.0f + __expf(-x));
}
__device__ __forceinline__ float tanh_e(float x) {
    return 1.0f - __fdividef(2.0f, __expf(2.0f * x) + 1.0f);
}
__device__ __forceinline__ void mma_bf16(float* d, const uint32_t* a,
                                         uint32_t b0, uint32_t b1) {
    asm volatile("mma.sync.aligned.m16n8k16.row.col.f32.bf16.bf16.f32 "
        "{%0,%1,%2,%3}, {%4,%5,%6,%7}, {%8,%9}, {%0,%1,%2,%3};"
        : "+f"(d[0]), "+f"(d[1]), "+f"(d[2]), "+f"(d[3])
        : "r"(a[0]), "r"(a[1]), "r"(a[2]), "r"(a[3]), "r"(b0), "r"(b1));
}
#define LDSM4(r0, r1, r2, r3, addr) \
    asm volatile("ldmatrix.sync.aligned.m8n8.x4.shared.b16 {%0,%1,%2,%3}, [%4];" \
        : "=r"(r0), "=r"(r1), "=r"(r2), "=r"(r3) : "r"(addr))
__device__ __forceinline__ void cp16(uint32_t sdst, const void* gsrc) {
    asm volatile("cp.async.cg.shared.global [%0], [%1], 16;"
                 :: "r"(sdst), "l"(gsrc) : "memory");
}
#define CP_COMMIT()  asm volatile("cp.async.commit_group;" ::: "memory")
#define CP_WAIT(n)   asm volatile("cp.async.wait_group %0;" :: "n"(n) : "memory")
#define BARC()       asm volatile("bar.sync 1, 256;" ::: "memory")
#define BARP()       asm volatile("bar.sync 2, 128;" ::: "memory")
__device__ __forceinline__ void red_release(int* p) {
    asm volatile("red.release.gpu.global.add.s32 [%0], 1;" :: "l"(p) : "memory");
}
__device__ __forceinline__ int ld_acquire(const int* p) {
    int v;
    asm volatile("ld.acquire.gpu.global.s32 %0, [%1];" : "=r"(v) : "l"(p) : "memory");
    return v;
}
__device__ __forceinline__ uint32_t smem_u32(const void* p) {
    uint32_t a;
    asm("{ .reg .u64 t; cvta.to.shared.u64 t, %1; cvt.u32.u64 %0, t; }" : "=r"(a) : "l"(p));
    return a;
}
__device__ __forceinline__ uint32_t pack_hi(float x, float y) {
    __nv_bfloat162 v(__float2bfloat16_rn(x), __float2bfloat16_rn(y));
    return *reinterpret_cast<uint32_t*>(&v);
}
__device__ __forceinline__ uint32_t pack_lo(float x, float y) {
    float hx = __bfloat162float(__float2bfloat16_rn(x));
    float hy = __bfloat162float(__float2bfloat16_rn(y));
    __nv_bfloat162 v(__float2bfloat16_rn(x - hx), __float2bfloat16_rn(y - hy));
    return *reinterpret_cast<uint32_t*>(&v);
}

// ---------------------------------------------------------------------------
// conv_a: fp32 -> hi/lo bf16, row remap r = t*512 + b
// ---------------------------------------------------------------------------
__global__ __launch_bounds__(256)
void conv_a(const float* __restrict__ inseq) {
    size_t i  = (size_t)blockIdx.x * 256 + threadIdx.x;
    size_t e0 = i * 4;
    int r = (int)(e0 >> 8), k = (int)(e0 & 255);
    int b = r & 511, t = r >> 9;
    float4 v = *reinterpret_cast<const float4*>(inseq + ((size_t)(b * SEQL + t)) * HID + k);
    *reinterpret_cast<uint2*>(&g_Ahi[e0]) = make_uint2(pack_hi(v.x, v.y), pack_hi(v.z, v.w));
    *reinterpret_cast<uint2*>(&g_Alo[e0]) = make_uint2(pack_lo(v.x, v.y), pack_lo(v.z, v.w));
}

// ---------------------------------------------------------------------------
// setup: Wc fold, splits (plain Wz; permuted Whh/Wc), corr, counters.
// ---------------------------------------------------------------------------
__global__ void setup_fold(const float* __restrict__ Whh, const float* __restrict__ Wih,
                           const float* __restrict__ Wlin, const float* __restrict__ blin) {
    const int j = blockIdx.x, k = threadIdx.x;
    const int gate = j >> 8, dim = j & 255;
    const int dt = dim >> 4, dl = dim & 15;
    const int nl = (dl >> 3) * 32 + gate * 8 + (dl & 7);
    const size_t pidx = ((size_t)(dt * 64 + nl)) * HID + k;

    float whh = Whh[j * HID + k];
    float wc  = whh;
#pragma unroll
    for (int m = 0; m < MF; m++)
        wc += Wih[j * KIN + m] * Wlin[m * HID + k];
    float wz = Wih[j * KIN + 17 + k];

    __nv_bfloat16 h;
    h = __float2bfloat16_rn(whh);
    g_Wq_hi[pidx] = h;
    g_Wq_lo[pidx] = __float2bfloat16_rn(whh - __bfloat162float(h));
    h = __float2bfloat16_rn(wc);
    g_Wp_hi[pidx] = h;
    g_Wp_lo[pidx] = __float2bfloat16_rn(wc - __bfloat162float(h));
    h = __float2bfloat16_rn(wz);
    g_Wzhi[j * HID + k] = h;
    g_Wzlo[j * HID + k] = __float2bfloat16_rn(wz - __bfloat162float(h));

    if (k == 0) {
        float c = 0.0f;
#pragma unroll
        for (int m = 0; m < MF; m++) c += Wih[j * KIN + m] * blin[m];
        g_corr[j] = c;
    }
    if (k == 1 && j < SEQL) g_zdone[j] = 0;
    if (j == 0 && k < NBT) g_cnt[k] = 0;
}

// ---------------------------------------------------------------------------
// fused persistent kernel: 128 CTAs (8 bt x 16 dt), 384 threads.
// smem (u32 offsets):
//   0        : Wc hi (64 x KPU)      P_U = 8448
//   P_U      : Wc lo
//   2P_U     : X hi                  (consumer h / h0 staging)
//   3P_U     : X lo
//   4P_U     : Z buffer (64 x 68 floats = 4352 u32)
//   4P_U+4352: producer A hi (32 x KPU = 4224)   +4224: A lo
//   +4224    : producer W hi (32 x KPU)          +4224: W lo
// ---------------------------------------------------------------------------
#define P_U     (64 * KPU)          // 8448
#define SZ_OFF  (4 * P_U)
#define SZ_U    (64 * 68)           // 4352
#define PR_U    (32 * KPU)          // 4224
#define PA_OFF  (SZ_OFF + SZ_U)
#define PW_OFF  (PA_OFF + 2 * PR_U)
#define SMEM_F  ((PW_OFF + 2 * PR_U) * 4)   // 220160 B

__global__ __launch_bounds__(384, 1)
void lstm_fused(const float* __restrict__ h0, const float* __restrict__ c0,
                const float* __restrict__ bih, const float* __restrict__ bhh) {
    extern __shared__ uint32_t smu[];
    const uint32_t ubase = smem_u32(smu);
    const int tid = threadIdx.x;

    if (tid >= 256) {
        // ===================== PRODUCER warps (8..11) ======================
        const int ptid = tid - 256;
        const int pw = ptid >> 5, pl = ptid & 31;
        const int pg = pl >> 2, pc = pl & 3;
        const int pmt = pw & 1, pnw = pw >> 1;

        const uint32_t paAd = ubase
            + (uint32_t)(PA_OFF + (pmt * 16 + (pl & 15)) * KPU) * 4 + (pl >> 4) * 16;
        const uint32_t pwBd = ubase
            + (uint32_t)(PW_OFF + (pnw * 16 + (pl >> 4) * 8 + (pl & 7)) * KPU) * 4
            + ((pl >> 3) & 1) * 16;
        const uint32_t PLO = (uint32_t)PR_U * 4;

        for (int rt = blockIdx.x; rt < NROWS / 32; rt += 128) {
            const int R0 = rt * 32;
            const int tt = R0 >> 9;
            // stage A rows (hi/lo)
            for (int idx = ptid; idx < 2048; idx += 128) {
                int sel = idx >> 10, row = (idx >> 5) & 31, seg = idx & 31;
                const __nv_bfloat16* src = sel ? g_Alo : g_Ahi;
                cp16(ubase + (uint32_t)(PA_OFF + sel * PR_U + row * KPU + seg * 4) * 4,
                     src + (size_t)(R0 + row) * HID + seg * 8);
            }
            CP_COMMIT(); CP_WAIT(0); BARP();

            for (int nc = 0; nc < 32; nc++) {
                // stage W chunk (32 gate-cols, hi/lo)
                for (int idx = ptid; idx < 2048; idx += 128) {
                    int sel = idx >> 10, row = (idx >> 5) & 31, seg = idx & 31;
                    const __nv_bfloat16* src = sel ? g_Wzlo : g_Wzhi;
                    cp16(ubase + (uint32_t)(PW_OFF + sel * PR_U + row * KPU + seg * 4) * 4,
                         src + (size_t)(nc * 32 + row) * HID + seg * 8);
                }
                CP_COMMIT(); CP_WAIT(0); BARP();

                float d2[2][4];
#pragma unroll
                for (int n8 = 0; n8 < 2; n8++)
#pragma unroll
                    for (int q = 0; q < 4; q++) d2[n8][q] = 0.0f;
                for (int p = 0; p < 3; p++) {
                    const uint32_t aoff = (p == 2) ? PLO : 0u;
                    const uint32_t boff = (p == 1) ? PLO : 0u;
#pragma unroll
                    for (int ks = 0; ks < 16; ks++) {
                        const uint32_t kb = ks * 32;
                        uint32_t u0, u1, u2, u3, a0[4];
                        LDSM4(a0[0], a0[1], a0[2], a0[3], paAd + aoff + kb);
                        LDSM4(u0, u1, u2, u3, pwBd + boff + kb);
                        mma_bf16(d2[0], a0, u0, u1);
                        mma_bf16(d2[1], a0, u2, u3);
                    }
                }
#pragma unroll
                for (int n8 = 0; n8 < 2; n8++) {
                    int col = nc * 32 + pnw * 16 + n8 * 8 + 2 * pc;
                    float bs0 = __ldg(bih + col) + __ldg(bhh + col);
                    float bs1 = __ldg(bih + col + 1) + __ldg(bhh + col + 1);
                    int r0 = R0 + pmt * 16 + pg;
                    *reinterpret_cast<float2*>(g_Z + (size_t)r0 * G4 + col) =
                        make_float2(d2[n8][0] + bs0, d2[n8][1] + bs1);
                    *reinterpret_cast<float2*>(g_Z + (size_t)(r0 + 8) * G4 + col) =
                        make_float2(d2[n8][2] + bs0, d2[n8][3] + bs1);
                }
                BARP();   // all producer warps done with this W chunk
            }
            __syncwarp();
            if (pl == 0) red_release(&g_zdone[tt]);   // 4/tile, 16 tiles/t -> 64
        }
        return;
    }

    // ======================== CONSUMER warps (0..7) ========================
    const int wid = tid >> 5, l = tid & 31;
    const int g = l >> 2, c = l & 3;
    const int mt = wid & 3, nt = wid >> 2;
    const int bt = blockIdx.x >> 4, dt = blockIdx.x & 15;
    const int bb0 = bt * BT, d0 = dt * 16;
    const int dl0 = nt * 8 + 2 * c;

    const uint32_t aXd = ubase
        + (uint32_t)(2 * P_U + (mt * 16 + (l & 15)) * KPU) * 4 + (l >> 4) * 16;
    uint32_t wBd[2];
#pragma unroll
    for (int p2 = 0; p2 < 2; p2++)
        wBd[p2] = ubase
            + (uint32_t)((nt * 32 + p2 * 16 + (l >> 4) * 8 + (l & 7)) * KPU) * 4
            + ((l >> 3) & 1) * 16;
    const uint32_t LOFF = (uint32_t)P_U * 4;

    float2 cst[2], cr[4];
#pragma unroll
    for (int rh = 0; rh < 2; rh++)
        cst[rh] = *reinterpret_cast<const float2*>(
            c0 + (size_t)(bb0 + mt * 16 + rh * 8 + g) * HID + d0 + dl0);
#pragma unroll
    for (int ga = 0; ga < 4; ga++)
        cr[ga] = *reinterpret_cast<const float2*>(g_corr + ga * HID + d0 + dl0);

    // stage permuted W_hh (step 0)
    for (int idx = tid; idx < 64 * 32; idx += 256) {
        int row = idx >> 5, seg = idx & 31;
        size_t src = (size_t)(dt * 64 + row) * HID + seg * 8;
        *reinterpret_cast<uint4*>(&smu[row * KPU + seg * 4]) =
            *reinterpret_cast<const uint4*>(g_Wq_hi + src);
        *reinterpret_cast<uint4*>(&smu[P_U + row * KPU + seg * 4]) =
            *reinterpret_cast<const uint4*>(g_Wq_lo + src);
    }

    for (int t = 0; t < SEQL; t++) {
        // wait for Z[t] production, then prefetch the slice into smem
        if (tid == 0) {
            while (ld_acquire(&g_zdone[t]) < 64) { }
        }
        BARC();
        {
            const float* zsrc = g_Z + ((size_t)t * BATCH + bb0) * G4 + d0;
            for (int idx = tid; idx < 1024; idx += 256) {
                int row = idx >> 4, ga = (idx >> 2) & 3, j = idx & 3;
                cp16(ubase + (uint32_t)(SZ_OFF + row * 68 + ga * 16 + j * 4) * 4,
                     zsrc + (size_t)row * G4 + ga * HID + j * 4);
            }
            CP_COMMIT();
        }

        // wait for h_{t-1} from all 16 dt-CTAs of this bt
        if (t > 0) {
            if (tid == 0) {
                const int target = 128 * t;
                while (ld_acquire(&g_cnt[bt]) < target) { }
            }
        }
        BARC();

        // stage X = h_{t-1}
        if (t == 0) {
            const float* src = h0 + (size_t)bb0 * HID;
            for (int idx = tid; idx < 64 * 64; idx += 256) {
                int row = idx >> 6, seg = idx & 63;
                float4 v = *reinterpret_cast<const float4*>(src + row * HID + seg * 4);
                int base = 2 * P_U + row * KPU + seg * 2;
                *reinterpret_cast<uint2*>(&smu[base]) =
                    make_uint2(pack_hi(v.x, v.y), pack_hi(v.z, v.w));
                *reinterpret_cast<uint2*>(&smu[base + P_U]) =
                    make_uint2(pack_lo(v.x, v.y), pack_lo(v.z, v.w));
            }
        } else {
            const size_t hb = ((size_t)(t - 1) * BATCH + bb0) * HID;
            for (int idx = tid; idx < 64 * 32 * 2; idx += 256) {
                int sel = idx >> 11, row = (idx >> 5) & 63, seg = idx & 31;
                const __nv_bfloat16* src = sel ? g_hh_lo : g_hh_hi;
                cp16(ubase + (uint32_t)(2 * P_U + sel * P_U + row * KPU + seg * 4) * 4,
                     src + hb + (size_t)row * HID + seg * 8);
            }
            CP_COMMIT();
        }
        CP_WAIT(0);
        BARC();

        // gates GEMM m16n32, K=256, 3-pass split
        float d[4][4];
#pragma unroll
        for (int n8 = 0; n8 < 4; n8++)
#pragma unroll
            for (int q = 0; q < 4; q++) d[n8][q] = 0.0f;
        for (int p = 0; p < 3; p++) {
            const uint32_t aoff = (p == 2) ? LOFF : 0u;
            const uint32_t boff = (p == 1) ? LOFF : 0u;
#pragma unroll
            for (int ks = 0; ks < 16; ks++) {
                const uint32_t kb = ks * 32;
                uint32_t u0, u1, u2, u3, v0, v1, v2, v3, a0[4];
                LDSM4(a0[0], a0[1], a0[2], a0[3], aXd + aoff + kb);
                LDSM4(u0, u1, u2, u3, wBd[0] + boff + kb);
                LDSM4(v0, v1, v2, v3, wBd[1] + boff + kb);
                mma_bf16(d[0], a0, u0, u1); mma_bf16(d[1], a0, u2, u3);
                mma_bf16(d[2], a0, v0, v1); mma_bf16(d[3], a0, v2, v3);
            }
        }

        // register-resident epilogue; Z from smem
        {
            const float* sZf = reinterpret_cast<const float*>(smu + SZ_OFF);
#pragma unroll
            for (int rh = 0; rh < 2; rh++) {
                int row = mt * 16 + rh * 8 + g;
                float* cs = &cst[rh].x;
                float hv[2];
#pragma unroll
                for (int j = 0; j < 2; j++) {
                    int q = rh * 2 + j;
                    float iv = d[0][q] + sZf[row * 68 + 0 * 16 + dl0 + j];
                    float fv = d[1][q] + sZf[row * 68 + 1 * 16 + dl0 + j];
                    float gv = d[2][q] + sZf[row * 68 + 2 * 16 + dl0 + j];
                    float ov = d[3][q] + sZf[row * 68 + 3 * 16 + dl0 + j];
                    if (t > 0) {
                        iv += (&cr[0].x)[j]; fv += (&cr[1].x)[j];
                        gv += (&cr[2].x)[j]; ov += (&cr[3].x)[j];
                    }
                    float cn = sigm(fv) * cs[j] + sigm(iv) * tanh_e(gv);
                    cs[j] = cn;
                    hv[j] = sigm(ov) * tanh_e(cn);
                }
                size_t base = ((size_t)t * BATCH + bb0 + row) * HID + d0 + dl0;
                reinterpret_cast<uint32_t*>(g_hh_hi)[base >> 1] = pack_hi(hv[0], hv[1]);
                reinterpret_cast<uint32_t*>(g_hh_lo)[base >> 1] = pack_lo(hv[0], hv[1]);
            }
        }
        __syncwarp();
        if (l == 0) red_release(&g_cnt[bt]);   // 8/CTA -> 128 per group per step

        // swap folded weights Wc in after step 0
        if (t == 0) {
            BARC();
            for (int idx = tid; idx < 64 * 32; idx += 256) {
                int row = idx >> 5, seg = idx & 31;
                size_t src = (size_t)(dt * 64 + row) * HID + seg * 8;
                *reinterpret_cast<uint4*>(&smu[row * KPU + seg * 4]) =
                    *reinterpret_cast<const uint4*>(g_Wp_hi + src);
                *reinterpret_cast<uint4*>(&smu[P_U + row * KPU + seg * 4]) =
                    *reinterpret_cast<const uint4*>(g_Wp_lo + src);
            }
        }
    }
}

// ---------------------------------------------------------------------------
// out_proj: h reconstructed = hi + lo
// ---------------------------------------------------------------------------
__global__ void out_proj(const float* __restrict__ Wlin, const float* __restrict__ blin,
                         float* __restrict__ out) {
    __shared__ float hs[16 * HID];
    const int t  = blockIdx.x;
    const int b0 = blockIdx.y * 16;
    const size_t base = ((size_t)t * BATCH + b0) * HID;
    const uint32_t* sH = reinterpret_cast<const uint32_t*>(g_hh_hi + base);
    const uint32_t* sL = reinterpret_cast<const uint32_t*>(g_hh_lo + base);
    for (int idx = threadIdx.x; idx < 16 * HID / 2; idx += 272) {
        uint32_t uh = sH[idx], ul = sL[idx];
        __nv_bfloat162 vh = *reinterpret_cast<__nv_bfloat162*>(&uh);
        __nv_bfloat162 vl = *reinterpret_cast<__nv_bfloat162*>(&ul);
        hs[2 * idx]     = __bfloat162float(vh.x) + __bfloat162float(vl.x);
        hs[2 * idx + 1] = __bfloat162float(vh.y) + __bfloat162float(vl.y);
    }
    __syncthreads();

    const int bl = threadIdx.x / MF;
    const int m  = threadIdx.x - bl * MF;
    const float* xr = hs + bl * HID;
    const float* wl = Wlin + m * HID;
    float s0 = 0, s1 = 0, s2 = 0, s3 = 0;
#pragma unroll 8
    for (int k = 0; k < HID; k += 4) {
        s0 += xr[k] * wl[k];         s1 += xr[k + 1] * wl[k + 1];
        s2 += xr[k + 2] * wl[k + 2]; s3 += xr[k + 3] * wl[k + 3];
    }
    out[((size_t)(b0 + bl) * SEQL + t) * MF + m] = blin[m] + s0 + s1 + s2 + s3;
}

// ---------------------------------------------------------------------------
extern "C" void kernel_launch(void* const* d_in, const int* in_sizes, int n_in,
                              void* d_out, int out_size) {
    const float* inseq = (const float*)d_in[0];
    const float* h0    = (const float*)d_in[1];
    const float* c0    = (const float*)d_in[2];
    const float* Wih   = (const float*)d_in[3];
    const float* Whh   = (const float*)d_in[4];
    const float* bih   = (const float*)d_in[5];
    const float* bhh   = (const float*)d_in[6];
    const float* Wlin  = (const float*)d_in[7];
    const float* blin  = (const float*)d_in[8];
    float* out = (float*)d_out;

    cudaFuncSetAttribute(lstm_fused, cudaFuncAttributeMaxDynamicSharedMemorySize,
                         SMEM_F);

    setup_fold<<<G4, HID>>>(Whh, Wih, Wlin, blin);
    conv_a<<<65536, 256>>>(inseq);
    lstm_fused<<<NBT * 16, 384, SMEM_F>>>(h0, c0, bih, bhh);
    out_proj<<<dim3(SEQL, 32), 272>>>(Wlin, blin, out);
}

// round 14
// speedup vs baseline: 1.1142x; 1.1142x over previous
#include <cuda_runtime.h>
#include <cuda_bf16.h>
#include <cstdint>
#include <math.h>

// ---------------------------------------------------------------------------
// LSTM decoder — mma.sync bf16 split hi/lo (3-pass), ldmatrix, cp.async.
// R14: persistent phase uses 256 small CTAs (16 bt x 16 dt, 128 thr, 110KB
// smem) at 2 CTAs/SM. Co-resident CTAs belong to different bt groups, so the
// HW scheduler overlaps one CTA's barrier spin with the other's GEMM.
// ---------------------------------------------------------------------------

#define BATCH 512
#define SEQL  512
#define HID   256
#define MF    17
#define G4    1024
#define KIN   273
#define NBT   16
#define BT    32
#define NROWS (SEQL * BATCH)
#define KPU   132            // u32 per bf16 row (264 bf16); 528B rows, LDSM-clean

typedef unsigned long long ull;

__device__ float          g_Z[(size_t)NROWS * G4];          // 1 GB
__device__ float          g_corr[G4];
__device__ int            g_cnt[NBT];
__device__ __nv_bfloat16  g_Ahi[(size_t)NROWS * HID];
__device__ __nv_bfloat16  g_Alo[(size_t)NROWS * HID];
__device__ __nv_bfloat16  g_hh_hi[(size_t)SEQL * BATCH * HID];
__device__ __nv_bfloat16  g_hh_lo[(size_t)SEQL * BATCH * HID];
__device__ __nv_bfloat16  g_Wzhi[G4 * HID], g_Wzlo[G4 * HID];   // z-proj (plain)
__device__ __nv_bfloat16  g_Wq_hi[G4 * HID], g_Wq_lo[G4 * HID]; // Whh (permuted)
__device__ __nv_bfloat16  g_Wp_hi[G4 * HID], g_Wp_lo[G4 * HID]; // Wc  (permuted)

__device__ __forceinline__ float sigm(float x) {
    return __fdividef(1.0f, 1.0f + __expf(-x));
}
__device__ __forceinline__ float tanh_e(float x) {
    return 1.0f - __fdividef(2.0f, __expf(2.0f * x) + 1.0f);
}
__device__ __forceinline__ void mma_bf16(float* d, const uint32_t* a,
                                         uint32_t b0, uint32_t b1) {
    asm volatile("mma.sync.aligned.m16n8k16.row.col.f32.bf16.bf16.f32 "
        "{%0,%1,%2,%3}, {%4,%5,%6,%7}, {%8,%9}, {%0,%1,%2,%3};"
        : "+f"(d[0]), "+f"(d[1]), "+f"(d[2]), "+f"(d[3])
        : "r"(a[0]), "r"(a[1]), "r"(a[2]), "r"(a[3]), "r"(b0), "r"(b1));
}
#define LDSM4(r0, r1, r2, r3, addr) \
    asm volatile("ldmatrix.sync.aligned.m8n8.x4.shared.b16 {%0,%1,%2,%3}, [%4];" \
        : "=r"(r0), "=r"(r1), "=r"(r2), "=r"(r3) : "r"(addr))
__device__ __forceinline__ void cp16(uint32_t sdst, const void* gsrc) {
    asm volatile("cp.async.cg.shared.global [%0], [%1], 16;"
                 :: "r"(sdst), "l"(gsrc) : "memory");
}
#define CP_COMMIT()  asm volatile("cp.async.commit_group;" ::: "memory")
#define CP_WAIT(n)   asm volatile("cp.async.wait_group %0;" :: "n"(n) : "memory")
__device__ __forceinline__ void red_release(int* p) {
    asm volatile("red.release.gpu.global.add.s32 [%0], 1;" :: "l"(p) : "memory");
}
__device__ __forceinline__ int ld_acquire(const int* p) {
    int v;
    asm volatile("ld.acquire.gpu.global.s32 %0, [%1];" : "=r"(v) : "l"(p) : "memory");
    return v;
}
__device__ __forceinline__ uint32_t smem_u32(const void* p) {
    uint32_t a;
    asm("{ .reg .u64 t; cvta.to.shared.u64 t, %1; cvt.u32.u64 %0, t; }" : "=r"(a) : "l"(p));
    return a;
}
__device__ __forceinline__ uint32_t pack_hi(float x, float y) {
    __nv_bfloat162 v(__float2bfloat16_rn(x), __float2bfloat16_rn(y));
    return *reinterpret_cast<uint32_t*>(&v);
}
__device__ __forceinline__ uint32_t pack_lo(float x, float y) {
    float hx = __bfloat162float(__float2bfloat16_rn(x));
    float hy = __bfloat162float(__float2bfloat16_rn(y));
    __nv_bfloat162 v(__float2bfloat16_rn(x - hx), __float2bfloat16_rn(y - hy));
    return *reinterpret_cast<uint32_t*>(&v);
}

// ---------------------------------------------------------------------------
// conv_a: fp32 -> hi/lo bf16, row remap r = t*512 + b
// ---------------------------------------------------------------------------
__global__ __launch_bounds__(256)
void conv_a(const float* __restrict__ inseq) {
    size_t i  = (size_t)blockIdx.x * 256 + threadIdx.x;
    size_t e0 = i * 4;
    int r = (int)(e0 >> 8), k = (int)(e0 & 255);
    int b = r & 511, t = r >> 9;
    float4 v = *reinterpret_cast<const float4*>(inseq + ((size_t)(b * SEQL + t)) * HID + k);
    *reinterpret_cast<uint2*>(&g_Ahi[e0]) = make_uint2(pack_hi(v.x, v.y), pack_hi(v.z, v.w));
    *reinterpret_cast<uint2*>(&g_Alo[e0]) = make_uint2(pack_lo(v.x, v.y), pack_lo(v.z, v.w));
}

// ---------------------------------------------------------------------------
// setup: Wc fold, splits (plain Wz; permuted Whh/Wc), corr, counters.
// Permutation: row j=(gate,dim) -> [dt][nl], nl = (dl>>3)*32 + gate*8 + (dl&7).
// ---------------------------------------------------------------------------
__global__ void setup_fold(const float* __restrict__ Whh, const float* __restrict__ Wih,
                           const float* __restrict__ Wlin, const float* __restrict__ blin) {
    const int j = blockIdx.x, k = threadIdx.x;
    const int gate = j >> 8, dim = j & 255;
    const int dt = dim >> 4, dl = dim & 15;
    const int nl = (dl >> 3) * 32 + gate * 8 + (dl & 7);
    const size_t pidx = ((size_t)(dt * 64 + nl)) * HID + k;

    float whh = Whh[j * HID + k];
    float wc  = whh;
#pragma unroll
    for (int m = 0; m < MF; m++)
        wc += Wih[j * KIN + m] * Wlin[m * HID + k];
    float wz = Wih[j * KIN + 17 + k];

    __nv_bfloat16 h;
    h = __float2bfloat16_rn(whh);
    g_Wq_hi[pidx] = h;
    g_Wq_lo[pidx] = __float2bfloat16_rn(whh - __bfloat162float(h));
    h = __float2bfloat16_rn(wc);
    g_Wp_hi[pidx] = h;
    g_Wp_lo[pidx] = __float2bfloat16_rn(wc - __bfloat162float(h));
    h = __float2bfloat16_rn(wz);
    g_Wzhi[j * HID + k] = h;
    g_Wzlo[j * HID + k] = __float2bfloat16_rn(wz - __bfloat162float(h));

    if (k == 0) {
        float c = 0.0f;
#pragma unroll
        for (int m = 0; m < MF; m++) c += Wih[j * KIN + m] * blin[m];
        g_corr[j] = c;
    }
    if (j == 0 && k < NBT) g_cnt[k] = 0;
}

// ---------------------------------------------------------------------------
// gemm_z: 4096 CTAs x (64 rows, 1024 cols), K=256, 3-pass split. (R10 proven)
// ---------------------------------------------------------------------------
#define GZ_A_U   (64 * KPU)
#define GZ_W_OFF (2 * GZ_A_U)
#define GZ_WT_U  (64 * KPU)
#define SMEM_GZ  ((2 * GZ_A_U + 4 * GZ_WT_U) * 4)

__global__ __launch_bounds__(256, 1)
void gemm_z(const float* __restrict__ bih, const float* __restrict__ bhh) {
    extern __shared__ uint32_t smu[];
    const uint32_t ubase = smem_u32(smu);
    const int tid = threadIdx.x;
    const int wid = tid >> 5, l = tid & 31;
    const int g = l >> 2, c = l & 3;
    const int mt = wid & 3, nh = wid >> 2;
    const int R0 = blockIdx.x * 64;

    for (int idx = tid; idx < 64 * 32 * 2; idx += 256) {
        int sel = idx >> 11, r2 = (idx >> 5) & 63, seg = idx & 31;
        const __nv_bfloat16* src = sel ? g_Alo : g_Ahi;
        cp16(ubase + (uint32_t)(sel * GZ_A_U + r2 * KPU + seg * 4) * 4,
             src + (size_t)(R0 + r2) * HID + seg * 8);
    }
    for (int idx = tid; idx < 64 * 32 * 2; idx += 256) {
        int sel = idx >> 11, r2 = (idx >> 5) & 63, seg = idx & 31;
        const __nv_bfloat16* src = sel ? g_Wzlo : g_Wzhi;
        cp16(ubase + (uint32_t)(GZ_W_OFF + sel * GZ_WT_U + r2 * KPU + seg * 4) * 4,
             src + (size_t)r2 * HID + seg * 8);
    }
    CP_COMMIT();

    const uint32_t aAd = ubase + (uint32_t)((mt * 16 + (l & 15)) * KPU) * 4 + (l >> 4) * 16;
    uint32_t wBd[2][2];
#pragma unroll
    for (int buf = 0; buf < 2; buf++)
#pragma unroll
        for (int p2 = 0; p2 < 2; p2++)
            wBd[buf][p2] = ubase
                + (uint32_t)(GZ_W_OFF + buf * 2 * GZ_WT_U
                             + (nh * 32 + p2 * 16 + (l >> 4) * 8 + (l & 7)) * KPU) * 4
                + ((l >> 3) & 1) * 16;
    const uint32_t ALO = (uint32_t)GZ_A_U * 4;
    const uint32_t WLO = (uint32_t)GZ_WT_U * 4;

    for (int nt = 0; nt < 16; nt++) {
        if (nt < 15) {
            int buf = (nt + 1) & 1;
            for (int idx = tid; idx < 64 * 32 * 2; idx += 256) {
                int sel = idx >> 11, r2 = (idx >> 5) & 63, seg = idx & 31;
                const __nv_bfloat16* src = sel ? g_Wzlo : g_Wzhi;
                cp16(ubase + (uint32_t)(GZ_W_OFF + (buf * 2 + sel) * GZ_WT_U
                                        + r2 * KPU + seg * 4) * 4,
                     src + (size_t)((nt + 1) * 64 + r2) * HID + seg * 8);
            }
            CP_COMMIT();
            CP_WAIT(1);
        } else {
            CP_WAIT(0);
        }
        __syncthreads();

        const int buf = nt & 1;
        float d[4][4];
#pragma unroll
        for (int n8 = 0; n8 < 4; n8++)
#pragma unroll
            for (int q = 0; q < 4; q++) d[n8][q] = 0.0f;

        for (int p = 0; p < 3; p++) {
            const uint32_t aoff = (p == 2) ? ALO : 0u;
            const uint32_t boff = (p == 1) ? WLO : 0u;
#pragma unroll
            for (int ks = 0; ks < 16; ks++) {
                const uint32_t kb = ks * 32;
                uint32_t u0, u1, u2, u3, v0, v1, v2, v3, a0[4];
                LDSM4(a0[0], a0[1], a0[2], a0[3], aAd + aoff + kb);
                LDSM4(u0, u1, u2, u3, wBd[buf][0] + boff + kb);
                LDSM4(v0, v1, v2, v3, wBd[buf][1] + boff + kb);
                mma_bf16(d[0], a0, u0, u1); mma_bf16(d[1], a0, u2, u3);
                mma_bf16(d[2], a0, v0, v1); mma_bf16(d[3], a0, v2, v3);
            }
        }

#pragma unroll
        for (int n8 = 0; n8 < 4; n8++) {
            int col = nt * 64 + nh * 32 + n8 * 8 + 2 * c;
            float bs0 = __ldg(bih + col) + __ldg(bhh + col);
            float bs1 = __ldg(bih + col + 1) + __ldg(bhh + col + 1);
            int r0 = R0 + mt * 16 + g;
            *reinterpret_cast<float2*>(g_Z + (size_t)r0 * G4 + col) =
                make_float2(d[n8][0] + bs0, d[n8][1] + bs1);
            *reinterpret_cast<float2*>(g_Z + (size_t)(r0 + 8) * G4 + col) =
                make_float2(d[n8][2] + bs0, d[n8][3] + bs1);
        }
        __syncthreads();
    }
}

// ---------------------------------------------------------------------------
// persistent: 256 CTAs (16 bt x 16 dt), 128 threads (4 warps m16n32),
// 2 CTAs/SM. Warp: mt = wid&1 (m16 of 32 rows), nt = wid>>1 (n32 of 64 cols).
// smem (u32): W hi|lo @0,P | X hi|lo @2P,3P | Z @4P (32 x 68 floats)
// ---------------------------------------------------------------------------
#define P_W_U   (64 * KPU)           // 8448
#define P_X_U   (32 * KPU)           // 4224
#define PX_OFF  (2 * P_W_U)
#define SZ_OFF  (2 * P_W_U + 2 * P_X_U)
#define SZ_U    (32 * 68)            // 2176
#define SMEM_P  ((SZ_OFF + SZ_U) * 4)   // 110080 B

__global__ __launch_bounds__(128, 2)
void lstm_persistent(const float* __restrict__ h0, const float* __restrict__ c0) {
    extern __shared__ uint32_t smu[];
    const uint32_t ubase = smem_u32(smu);
    const int tid = threadIdx.x;
    const int wid = tid >> 5, l = tid & 31;
    const int g = l >> 2, c = l & 3;
    const int mt = wid & 1, nt = wid >> 1;
    const int bt = blockIdx.x >> 4, dt = blockIdx.x & 15;
    const int bb0 = bt * BT, d0 = dt * 16;
    const int dl0 = nt * 8 + 2 * c;

    const uint32_t aXd = ubase
        + (uint32_t)(PX_OFF + (mt * 16 + (l & 15)) * KPU) * 4 + (l >> 4) * 16;
    uint32_t wBd[2];
#pragma unroll
    for (int p2 = 0; p2 < 2; p2++)
        wBd[p2] = ubase
            + (uint32_t)((nt * 32 + p2 * 16 + (l >> 4) * 8 + (l & 7)) * KPU) * 4
            + ((l >> 3) & 1) * 16;
    const uint32_t WLO = (uint32_t)P_W_U * 4;
    const uint32_t XLO = (uint32_t)P_X_U * 4;

    // per-thread state: rows mt*16 + rh*8 + g (rh=0,1), dims d0+dl0, +1
    float2 cst[2], cr[4];
#pragma unroll
    for (int rh = 0; rh < 2; rh++)
        cst[rh] = *reinterpret_cast<const float2*>(
            c0 + (size_t)(bb0 + mt * 16 + rh * 8 + g) * HID + d0 + dl0);
#pragma unroll
    for (int ga = 0; ga < 4; ga++)
        cr[ga] = *reinterpret_cast<const float2*>(g_corr + ga * HID + d0 + dl0);

    // stage permuted W_hh (step 0)
    for (int idx = tid; idx < 64 * 32; idx += 128) {
        int row = idx >> 5, seg = idx & 31;
        size_t src = (size_t)(dt * 64 + row) * HID + seg * 8;
        *reinterpret_cast<uint4*>(&smu[row * KPU + seg * 4]) =
            *reinterpret_cast<const uint4*>(g_Wq_hi + src);
        *reinterpret_cast<uint4*>(&smu[P_W_U + row * KPU + seg * 4]) =
            *reinterpret_cast<const uint4*>(g_Wq_lo + src);
    }

    for (int t = 0; t < SEQL; t++) {
        // Z prefetch into smem via cp.async, BEFORE the spin (h-independent)
        {
            const float* zsrc = g_Z + ((size_t)t * BATCH + bb0) * G4 + d0;
            for (int idx = tid; idx < 512; idx += 128) {
                int row = idx >> 4, ga = (idx >> 2) & 3, j = idx & 3;
                cp16(ubase + (uint32_t)(SZ_OFF + row * 68 + ga * 16 + j * 4) * 4,
                     zsrc + (size_t)row * G4 + ga * HID + j * 4);
            }
            CP_COMMIT();
        }

        if (t > 0) {
            if (tid == 0) {
                const int target = 64 * t;     // 4 warps x 16 dt CTAs
                while (ld_acquire(&g_cnt[bt]) < target) { }
            }
            __syncthreads();
        }

        // stage X = h_{t-1}
        if (t == 0) {
            const float* src = h0 + (size_t)bb0 * HID;
            for (int idx = tid; idx < 32 * 64; idx += 128) {
                int row = idx >> 6, seg = idx & 63;
                float4 v = *reinterpret_cast<const float4*>(src + row * HID + seg * 4);
                int base = PX_OFF + row * KPU + seg * 2;
                *reinterpret_cast<uint2*>(&smu[base]) =
                    make_uint2(pack_hi(v.x, v.y), pack_hi(v.z, v.w));
                *reinterpret_cast<uint2*>(&smu[base + P_X_U]) =
                    make_uint2(pack_lo(v.x, v.y), pack_lo(v.z, v.w));
            }
        } else {
            const size_t hb = ((size_t)(t - 1) * BATCH + bb0) * HID;
            for (int idx = tid; idx < 32 * 32 * 2; idx += 128) {
                int sel = idx >> 10, row = (idx >> 5) & 31, seg = idx & 31;
                const __nv_bfloat16* src = sel ? g_hh_lo : g_hh_hi;
                cp16(ubase + (uint32_t)(PX_OFF + sel * P_X_U + row * KPU + seg * 4) * 4,
                     src + hb + (size_t)row * HID + seg * 8);
            }
            CP_COMMIT();
        }
        CP_WAIT(0);
        __syncthreads();

        // gates GEMM m16n32, K=256, 3-pass split
        float d[4][4];
#pragma unroll
        for (int n8 = 0; n8 < 4; n8++)
#pragma unroll
            for (int q = 0; q < 4; q++) d[n8][q] = 0.0f;

        for (int p = 0; p < 3; p++) {
            const uint32_t aoff = (p == 2) ? XLO : 0u;
            const uint32_t boff = (p == 1) ? WLO : 0u;
#pragma unroll
            for (int ks = 0; ks < 16; ks++) {
                const uint32_t kb = ks * 32;
                uint32_t u0, u1, u2, u3, v0, v1, v2, v3, a0[4];
                LDSM4(a0[0], a0[1], a0[2], a0[3], aXd + aoff + kb);
                LDSM4(u0, u1, u2, u3, wBd[0] + boff + kb);
                LDSM4(v0, v1, v2, v3, wBd[1] + boff + kb);
                mma_bf16(d[0], a0, u0, u1); mma_bf16(d[1], a0, u2, u3);
                mma_bf16(d[2], a0, v0, v1); mma_bf16(d[3], a0, v2, v3);
            }
        }

        // register-resident epilogue; Z from smem
        {
            const float* sZf = reinterpret_cast<const float*>(smu + SZ_OFF);
#pragma unroll
            for (int rh = 0; rh < 2; rh++) {
                int row = mt * 16 + rh * 8 + g;
                float* cs = &cst[rh].x;
                float hv[2];
#pragma unroll
                for (int j = 0; j < 2; j++) {
                    int q = rh * 2 + j;
                    float iv = d[0][q] + sZf[row * 68 + 0 * 16 + dl0 + j];
                    float fv = d[1][q] + sZf[row * 68 + 1 * 16 + dl0 + j];
                    float gv = d[2][q] + sZf[row * 68 + 2 * 16 + dl0 + j];
                    float ov = d[3][q] + sZf[row * 68 + 3 * 16 + dl0 + j];
                    if (t > 0) {
                        iv += (&cr[0].x)[j]; fv += (&cr[1].x)[j];
                        gv += (&cr[2].x)[j]; ov += (&cr[3].x)[j];
                    }
                    float cn = sigm(fv) * cs[j] + sigm(iv) * tanh_e(gv);
                    cs[j] = cn;
                    hv[j] = sigm(ov) * tanh_e(cn);
                }
                size_t base = ((size_t)t * BATCH + bb0 + row) * HID + d0 + dl0;
                reinterpret_cast<uint32_t*>(g_hh_hi)[base >> 1] = pack_hi(hv[0], hv[1]);
                reinterpret_cast<uint32_t*>(g_hh_lo)[base >> 1] = pack_lo(hv[0], hv[1]);
            }
        }
        __syncwarp();
        if (l == 0) red_release(&g_cnt[bt]);   // 4/CTA -> 64 per bt per step

        // swap folded weights Wc in after step 0
        if (t == 0) {
            __syncthreads();
            for (int idx = tid; idx < 64 * 32; idx += 128) {
                int row = idx >> 5, seg = idx & 31;
                size_t src = (size_t)(dt * 64 + row) * HID + seg * 8;
                *reinterpret_cast<uint4*>(&smu[row * KPU + seg * 4]) =
                    *reinterpret_cast<const uint4*>(g_Wp_hi + src);
                *reinterpret_cast<uint4*>(&smu[P_W_U + row * KPU + seg * 4]) =
                    *reinterpret_cast<const uint4*>(g_Wp_lo + src);
            }
        }
    }
}

// ---------------------------------------------------------------------------
// out_proj: h reconstructed = hi + lo
// ---------------------------------------------------------------------------
__global__ void out_proj(const float* __restrict__ Wlin, const float* __restrict__ blin,
                         float* __restrict__ out) {
    __shared__ float hs[16 * HID];
    const int t  = blockIdx.x;
    const int b0 = blockIdx.y * 16;
    const size_t base = ((size_t)t * BATCH + b0) * HID;
    const uint32_t* sH = reinterpret_cast<const uint32_t*>(g_hh_hi + base);
    const uint32_t* sL = reinterpret_cast<const uint32_t*>(g_hh_lo + base);
    for (int idx = threadIdx.x; idx < 16 * HID / 2; idx += 272) {
        uint32_t uh = sH[idx], ul = sL[idx];
        __nv_bfloat162 vh = *reinterpret_cast<__nv_bfloat162*>(&uh);
        __nv_bfloat162 vl = *reinterpret_cast<__nv_bfloat162*>(&ul);
        hs[2 * idx]     = __bfloat162float(vh.x) + __bfloat162float(vl.x);
        hs[2 * idx + 1] = __bfloat162float(vh.y) + __bfloat162float(vl.y);
    }
    __syncthreads();

    const int bl = threadIdx.x / MF;
    const int m  = threadIdx.x - bl * MF;
    const float* xr = hs + bl * HID;
    const float* wl = Wlin + m * HID;
    float s0 = 0, s1 = 0, s2 = 0, s3 = 0;
#pragma unroll 8
    for (int k = 0; k < HID; k += 4) {
        s0 += xr[k] * wl[k];         s1 += xr[k + 1] * wl[k + 1];
        s2 += xr[k + 2] * wl[k + 2]; s3 += xr[k + 3] * wl[k + 3];
    }
    out[((size_t)(b0 + bl) * SEQL + t) * MF + m] = blin[m] + s0 + s1 + s2 + s3;
}

// ---------------------------------------------------------------------------
extern "C" void kernel_launch(void* const* d_in, const int* in_sizes, int n_in,
                              void* d_out, int out_size) {
    const float* inseq = (const float*)d_in[0];
    const float* h0    = (const float*)d_in[1];
    const float* c0    = (const float*)d_in[2];
    const float* Wih   = (const float*)d_in[3];
    const float* Whh   = (const float*)d_in[4];
    const float* bih   = (const float*)d_in[5];
    const float* bhh   = (const float*)d_in[6];
    const float* Wlin  = (const float*)d_in[7];
    const float* blin  = (const float*)d_in[8];
    float* out = (float*)d_out;

    cudaFuncSetAttribute(gemm_z, cudaFuncAttributeMaxDynamicSharedMemorySize, SMEM_GZ);
    cudaFuncSetAttribute(lstm_persistent, cudaFuncAttributeMaxDynamicSharedMemorySize, SMEM_P);

    setup_fold<<<G4, HID>>>(Whh, Wih, Wlin, blin);
    conv_a<<<65536, 256>>>(inseq);
    gemm_z<<<4096, 256, SMEM_GZ>>>(bih, bhh);
    lstm_persistent<<<NBT * 16, 128, SMEM_P>>>(h0, c0);
    out_proj<<<dim3(SEQL, 32), 272>>>(Wlin, blin, out);
}